// round 5
// baseline (speedup 1.0000x reference)
#include <cuda_runtime.h>
#include <cuda_bf16.h>
#include <cstdint>

#define Nn 50000
#define Ee 1600000
#define Hh 64
#define INC 7
#define ED 4
#define Gg 256
#define FCH 128
#define NC 2
#define CH 32                      // edges per 16-lane group

typedef unsigned long long u64;

// ---------------- device scratch ----------------------------------------------------
__device__ __align__(16) float g_xl[Nn * Hh];
__device__ __align__(16) float g_xr[Nn * Hh];
__device__ __align__(16) float g_agg[Nn * Hh];
__device__ float g_den[Nn];
__device__ float g_pool[Gg * Hh];
__device__ float g_cnt[Gg];
__device__ int   g_cur[Nn];                    // zero-init; re-zeroed by head_kernel
__device__ int   g_off[Nn + 1];
__device__ __align__(16) int    g_sd[2 * Ee + 16];   // (src,dst) pairs, dst-sorted (+pad)
__device__ __align__(16) float4 g_eaS[Ee];           // edge_attr permuted to sorted order

// ---------------- f32x2 packed helpers ----------------------------------------------
__device__ __forceinline__ u64 pk(float a, float b) {
    u64 d; asm("mov.b64 %0,{%1,%2};" : "=l"(d) : "f"(a), "f"(b)); return d;
}
__device__ __forceinline__ void upk(u64 s, float& a, float& b) {
    asm("mov.b64 {%0,%1},%2;" : "=f"(a), "=f"(b) : "l"(s));
}
__device__ __forceinline__ u64 fma2(u64 a, u64 b, u64 c) {
    u64 d; asm("fma.rn.f32x2 %0,%1,%2,%3;" : "=l"(d) : "l"(a), "l"(b), "l"(c)); return d;
}
__device__ __forceinline__ u64 add2(u64 a, u64 b) {
    u64 d; asm("add.rn.f32x2 %0,%1,%2;" : "=l"(d) : "l"(a), "l"(b)); return d;
}
__device__ __forceinline__ u64 mul2(u64 a, u64 b) {
    u64 d; asm("mul.rn.f32x2 %0,%1,%2;" : "=l"(d) : "l"(a), "l"(b)); return d;
}
#define MABS 0x7fffffff7fffffffULL
#define C06  0x3f19999a3f19999aULL   /* {0.6f,0.6f} */
#define C04  0x3ecccccd3ecccccdULL   /* {0.4f,0.4f} */

// ---------------- proj layer 0: tiled GEMM (K=7) + fused dst histogram -------------
__global__ __launch_bounds__(256) void proj0_gemm_kernel(const float* __restrict__ x,
                                                         const float* __restrict__ Wl,
                                                         const float* __restrict__ bl,
                                                         const float* __restrict__ Wr,
                                                         const float* __restrict__ br,
                                                         const int* __restrict__ ei) {
    __shared__ float sX[64][8];     // [node][k], k<7 used
    __shared__ float sW[7][128];    // [k][col]  (Wl || Wr)
    int t = threadIdx.x;
    int m0 = blockIdx.x * 64;

    // fused histogram: 8 edges per thread (Ee % 8 == 0)
    {
        int i = (blockIdx.x * 256 + t) * 8;
        if (i < Ee) {
            int4 da = *reinterpret_cast<const int4*>(ei + Ee + i);
            int4 db = *reinterpret_cast<const int4*>(ei + Ee + i + 4);
            atomicAdd(&g_cur[da.x], 1); atomicAdd(&g_cur[da.y], 1);
            atomicAdd(&g_cur[da.z], 1); atomicAdd(&g_cur[da.w], 1);
            atomicAdd(&g_cur[db.x], 1); atomicAdd(&g_cur[db.y], 1);
            atomicAdd(&g_cur[db.z], 1); atomicAdd(&g_cur[db.w], 1);
        }
    }
    // load X tile (64 x 7)
    for (int idx = t; idx < 64 * INC; idx += 256) {
        int r = idx / INC;
        int k = idx - r * INC;
        int n = m0 + r;
        sX[r][k] = (n < Nn) ? x[n * INC + k] : 0.0f;
    }
    // load W (7 x 128)
    for (int idx = t; idx < INC * 128; idx += 256) {
        int k = idx >> 7;
        int c = idx & 127;
        sW[k][c] = (c < 64) ? Wl[k * 64 + c] : Wr[k * 64 + (c - 64)];
    }
    __syncthreads();

    int tm = t & 15;
    int tn = t >> 4;
    float acc[4][8];
#pragma unroll
    for (int i = 0; i < 4; i++)
#pragma unroll
        for (int j = 0; j < 8; j++) acc[i][j] = 0.0f;
#pragma unroll
    for (int k = 0; k < INC; k++) {
        float av[4];
#pragma unroll
        for (int i = 0; i < 4; i++) av[i] = sX[tm * 4 + i][k];
        float4 b0 = *reinterpret_cast<const float4*>(&sW[k][tn * 8]);
        float4 b1 = *reinterpret_cast<const float4*>(&sW[k][tn * 8 + 4]);
        float bv[8] = {b0.x, b0.y, b0.z, b0.w, b1.x, b1.y, b1.z, b1.w};
#pragma unroll
        for (int i = 0; i < 4; i++)
#pragma unroll
            for (int j = 0; j < 8; j++)
                acc[i][j] = fmaf(av[i], bv[j], acc[i][j]);
    }
#pragma unroll
    for (int i = 0; i < 4; i++) {
        int n = m0 + tm * 4 + i;
        if (n >= Nn) break;
#pragma unroll
        for (int j = 0; j < 8; j++) {
            int c = tn * 8 + j;
            if (c < 64) g_xl[n * 64 + c] = acc[i][j] + bl[c];
            else        g_xr[n * 64 + (c - 64)] = acc[i][j] + br[c - 64];
        }
    }
    // zero accumulators for layer 0 edge pass
#pragma unroll
    for (int i = 0; i < 16; i++) {
        int idx = t + i * 256;
        int n = m0 + (idx >> 6);
        if (n < Nn) g_agg[n * 64 + (idx & 63)] = 0.0f;
    }
    if (t < 64 && m0 + t < Nn) g_den[m0 + t] = 0.0f;
}

// ---------------- single-block exclusive scan (also zeros pool buffers) ------------
__global__ __launch_bounds__(1024) void scan_kernel() {
    __shared__ int sp[1024];
    int t = threadIdx.x;
    const int CHK = (Nn + 1023) / 1024;   // 49
    int base = t * CHK;
    int s = 0;
    for (int i = 0; i < CHK; i++) {
        int j = base + i;
        if (j < Nn) s += g_cur[j];
    }
    sp[t] = s;
    __syncthreads();
    for (int off = 1; off < 1024; off <<= 1) {
        int v = (t >= off) ? sp[t - off] : 0;
        __syncthreads();
        sp[t] += v;
        __syncthreads();
    }
    int run = sp[t] - s;
    for (int i = 0; i < CHK; i++) {
        int j = base + i;
        if (j < Nn) {
            int c = g_cur[j];
            g_off[j] = run;
            g_cur[j] = run;
            run += c;
        }
    }
    if (t == 0) g_off[Nn] = Ee;
    for (int i = t; i < Gg * Hh; i += 1024) g_pool[i] = 0.0f;
    if (t < Gg) g_cnt[t] = 0.0f;
}

// ---------------- counting sort: scatter (unroll 8) --------------------------------
__global__ void scatter_kernel(const int* __restrict__ ei, const float* __restrict__ ea) {
    int i = (blockIdx.x * blockDim.x + threadIdx.x) * 8;
    if (i >= Ee) return;
    int4 sa = *reinterpret_cast<const int4*>(ei + i);
    int4 sb = *reinterpret_cast<const int4*>(ei + i + 4);
    int4 da = *reinterpret_cast<const int4*>(ei + Ee + i);
    int4 db = *reinterpret_cast<const int4*>(ei + Ee + i + 4);
    int ss[8] = {sa.x, sa.y, sa.z, sa.w, sb.x, sb.y, sb.z, sb.w};
    int dd[8] = {da.x, da.y, da.z, da.w, db.x, db.y, db.z, db.w};
    float4 ev[8];
#pragma unroll
    for (int k = 0; k < 8; k++) ev[k] = *reinterpret_cast<const float4*>(ea + 4 * (i + k));
    int pp[8];
#pragma unroll
    for (int k = 0; k < 8; k++) pp[k] = atomicAdd(&g_cur[dd[k]], 1);
#pragma unroll
    for (int k = 0; k < 8; k++) {
        *reinterpret_cast<int2*>(g_sd + 2 * pp[k]) = make_int2(ss[k], dd[k]);
        g_eaS[pp[k]] = ev[k];
    }
}

// ---------------- packed score: pre = xl + xr + ea@We, leaky, dot att --------------
__device__ __forceinline__ float score_pk(float4 xl, u64 xr2a, u64 xr2b, float4 ea,
                                          const u64* w2a, const u64* w2b,
                                          u64 at2a, u64 at2b) {
    u64 e0 = pk(ea.x, ea.x), e1 = pk(ea.y, ea.y), e2 = pk(ea.z, ea.z), e3 = pk(ea.w, ea.w);
    u64 pa = add2(pk(xl.x, xl.y), xr2a);
    pa = fma2(e0, w2a[0], pa); pa = fma2(e1, w2a[1], pa);
    pa = fma2(e2, w2a[2], pa); pa = fma2(e3, w2a[3], pa);
    u64 pb = add2(pk(xl.z, xl.w), xr2b);
    pb = fma2(e0, w2b[0], pb); pb = fma2(e1, w2b[1], pb);
    pb = fma2(e2, w2b[2], pb); pb = fma2(e3, w2b[3], pb);
    u64 la = fma2(pa & MABS, C04, mul2(pa, C06));   // leaky = 0.6x + 0.4|x|
    u64 lb = fma2(pb & MABS, C04, mul2(pb, C06));
    u64 s2 = fma2(lb, at2b, mul2(la, at2a));
    float lo, hi; upk(s2, lo, hi);
    return lo + hi;
}

// ---------------- quad-batched edge pass over dst-sorted edges ---------------------
__global__ __launch_bounds__(256) void edge_q_kernel(const float* __restrict__ We,
                                                     const float* __restrict__ att) {
    __shared__ float sWe[Hh * ED];
    __shared__ float sAtt[Hh];
    int t = threadIdx.x;
    if (t < Hh) {
        sAtt[t] = att[t];
#pragma unroll
        for (int k = 0; k < ED; k++) sWe[t * ED + k] = We[k * Hh + t];
    }
    __syncthreads();

    int lid = t & 31;
    int grp = (blockIdx.x * 8 + (t >> 5)) * 2 + (lid >> 4);
    int sl = lid & 15;
    int h = sl * 4;
    unsigned gmask = 0xFFFFu << (lid & 16);   // this 16-lane half's mask
    int base = grp * CH;
    if (base >= Ee) return;

    u64 w2a[4], w2b[4];
#pragma unroll
    for (int k = 0; k < ED; k++) {
        w2a[k] = pk(sWe[h * ED + k], sWe[(h + 1) * ED + k]);
        w2b[k] = pk(sWe[(h + 2) * ED + k], sWe[(h + 3) * ED + k]);
    }
    u64 at2a = pk(sAtt[h], sAtt[h + 1]);
    u64 at2b = pk(sAtt[h + 2], sAtt[h + 3]);

    int cur = -1;
    u64 xr2a = 0, xr2b = 0;
    u64 acc_a = 0, acc_b = 0;   // 0ull == {0.f,0.f}
    float den = 0.0f;

#define FLUSH() do { if (cur >= 0) { \
        float a0,a1,a2,a3; upk(acc_a,a0,a1); upk(acc_b,a2,a3); \
        float* dp = g_agg + (cur << 6) + h; \
        asm volatile("red.global.add.v4.f32 [%0], {%1, %2, %3, %4};" \
                     :: "l"(dp), "f"(a0), "f"(a1), "f"(a2), "f"(a3) : "memory"); \
        if (sl == 0) asm volatile("red.global.add.f32 [%0], %1;" \
                     :: "l"(g_den + cur), "f"(den) : "memory"); } } while (0)

    int4 p01 = *reinterpret_cast<const int4*>(g_sd + 2 * base);
    int4 p23 = *reinterpret_cast<const int4*>(g_sd + 2 * base + 4);

#pragma unroll 1
    for (int q = 0; q < CH; q += 4) {
        int e = base + q;
        int s0 = p01.x, d0 = p01.y, s1 = p01.z, d1 = p01.w;
        int s2i = p23.x, d2 = p23.y, s3 = p23.z, d3 = p23.w;
        p01 = *reinterpret_cast<const int4*>(g_sd + 2 * (e + 4));
        p23 = *reinterpret_cast<const int4*>(g_sd + 2 * (e + 4) + 4);

        float4 xl0 = *reinterpret_cast<const float4*>(g_xl + (s0 << 6) + h);
        float4 xl1 = *reinterpret_cast<const float4*>(g_xl + (s1 << 6) + h);
        float4 xl2 = *reinterpret_cast<const float4*>(g_xl + (s2i << 6) + h);
        float4 xl3 = *reinterpret_cast<const float4*>(g_xl + (s3 << 6) + h);
        float4 ea0 = g_eaS[e + 0];
        float4 ea1 = g_eaS[e + 1];
        float4 ea2 = g_eaS[e + 2];
        float4 ea3 = g_eaS[e + 3];

        if (d3 == cur) {
            // fast path: whole quad in current run (dst sorted => all == cur)
            float pp0 = score_pk(xl0, xr2a, xr2b, ea0, w2a, w2b, at2a, at2b);
            float pp1 = score_pk(xl1, xr2a, xr2b, ea1, w2a, w2b, at2a, at2b);
            float pp2 = score_pk(xl2, xr2a, xr2b, ea2, w2a, w2b, at2a, at2b);
            float pp3 = score_pk(xl3, xr2a, xr2b, ea3, w2a, w2b, at2a, at2b);
            pp0 += __shfl_xor_sync(gmask, pp0, 8);
            pp1 += __shfl_xor_sync(gmask, pp1, 8);
            pp2 += __shfl_xor_sync(gmask, pp2, 8);
            pp3 += __shfl_xor_sync(gmask, pp3, 8);
            pp0 += __shfl_xor_sync(gmask, pp0, 4);
            pp1 += __shfl_xor_sync(gmask, pp1, 4);
            pp2 += __shfl_xor_sync(gmask, pp2, 4);
            pp3 += __shfl_xor_sync(gmask, pp3, 4);
            pp0 += __shfl_xor_sync(gmask, pp0, 2);
            pp1 += __shfl_xor_sync(gmask, pp1, 2);
            pp2 += __shfl_xor_sync(gmask, pp2, 2);
            pp3 += __shfl_xor_sync(gmask, pp3, 2);
            pp0 += __shfl_xor_sync(gmask, pp0, 1);
            pp1 += __shfl_xor_sync(gmask, pp1, 1);
            pp2 += __shfl_xor_sync(gmask, pp2, 1);
            pp3 += __shfl_xor_sync(gmask, pp3, 1);
            float ex0 = __expf(pp0);
            float ex1 = __expf(pp1);
            float ex2 = __expf(pp2);
            float ex3 = __expf(pp3);
            acc_a = fma2(pk(xl0.x, xl0.y), pk(ex0, ex0), acc_a);
            acc_b = fma2(pk(xl0.z, xl0.w), pk(ex0, ex0), acc_b);
            acc_a = fma2(pk(xl1.x, xl1.y), pk(ex1, ex1), acc_a);
            acc_b = fma2(pk(xl1.z, xl1.w), pk(ex1, ex1), acc_b);
            acc_a = fma2(pk(xl2.x, xl2.y), pk(ex2, ex2), acc_a);
            acc_b = fma2(pk(xl2.z, xl2.w), pk(ex2, ex2), acc_b);
            acc_a = fma2(pk(xl3.x, xl3.y), pk(ex3, ex3), acc_a);
            acc_b = fma2(pk(xl3.z, xl3.w), pk(ex3, ex3), acc_b);
            den += ex0 + ex1 + ex2 + ex3;
        } else {
            // slow path: run boundary inside quad — handle edges sequentially
            int sv[4] = {s0, s1, s2i, s3};
            int dv[4] = {d0, d1, d2, d3};
            float4 xlv[4] = {xl0, xl1, xl2, xl3};
            float4 eav[4] = {ea0, ea1, ea2, ea3};
#pragma unroll
            for (int j = 0; j < 4; j++) {
                int d = dv[j];
                if (d != cur) {
                    FLUSH();
                    cur = d;
                    float4 xr4 = *reinterpret_cast<const float4*>(g_xr + (d << 6) + h);
                    xr2a = pk(xr4.x, xr4.y);
                    xr2b = pk(xr4.z, xr4.w);
                    acc_a = 0; acc_b = 0; den = 0.0f;
                }
                float p = score_pk(xlv[j], xr2a, xr2b, eav[j], w2a, w2b, at2a, at2b);
                p += __shfl_xor_sync(gmask, p, 8);
                p += __shfl_xor_sync(gmask, p, 4);
                p += __shfl_xor_sync(gmask, p, 2);
                p += __shfl_xor_sync(gmask, p, 1);
                float ex = __expf(p);
                acc_a = fma2(pk(xlv[j].x, xlv[j].y), pk(ex, ex), acc_a);
                acc_b = fma2(pk(xlv[j].z, xlv[j].w), pk(ex, ex), acc_b);
                den += ex;
                (void)sv;
            }
        }
    }
    FLUSH();
#undef FLUSH
}

// ---------------- proj layer 1: tiled GEMM, elu(layer0) fused into X load ----------
__global__ __launch_bounds__(256) void proj1_gemm_kernel(const float* __restrict__ Wl,
                                                         const float* __restrict__ bl,
                                                         const float* __restrict__ Wr,
                                                         const float* __restrict__ br,
                                                         const float* __restrict__ bias0) {
    __shared__ float sXT[32][68];
    __shared__ float sW[32][128];
    int t = threadIdx.x;
    int m0 = blockIdx.x * 64;
    int tm = t & 15;
    int tn = t >> 4;
    float acc[4][8];
#pragma unroll
    for (int i = 0; i < 4; i++)
#pragma unroll
        for (int j = 0; j < 8; j++) acc[i][j] = 0.0f;

    for (int k0 = 0; k0 < 64; k0 += 32) {
#pragma unroll
        for (int i = 0; i < 8; i++) {
            int idx = t + i * 256;
            int r = idx >> 5;
            int kk = idx & 31;
            int n = m0 + r;
            float v = 0.0f;
            if (n < Nn) {
                float a = g_agg[n * 64 + k0 + kk];
                float vv = a / (g_den[n] + 1e-16f) + bias0[k0 + kk];
                v = vv > 0.0f ? vv : expm1f(vv);
            }
            sXT[kk][r] = v;
        }
#pragma unroll
        for (int i = 0; i < 16; i++) {
            int idx = t + i * 256;
            int kk = idx >> 7;
            int n = idx & 127;
            sW[kk][n] = (n < 64) ? Wl[(k0 + kk) * 64 + n] : Wr[(k0 + kk) * 64 + (n - 64)];
        }
        __syncthreads();
#pragma unroll
        for (int kk = 0; kk < 32; kk++) {
            float4 a = *reinterpret_cast<const float4*>(&sXT[kk][tm * 4]);
            float4 b0 = *reinterpret_cast<const float4*>(&sW[kk][tn * 8]);
            float4 b1 = *reinterpret_cast<const float4*>(&sW[kk][tn * 8 + 4]);
            float av[4] = {a.x, a.y, a.z, a.w};
            float bv[8] = {b0.x, b0.y, b0.z, b0.w, b1.x, b1.y, b1.z, b1.w};
#pragma unroll
            for (int i = 0; i < 4; i++)
#pragma unroll
                for (int j = 0; j < 8; j++)
                    acc[i][j] = fmaf(av[i], bv[j], acc[i][j]);
        }
        __syncthreads();
    }
#pragma unroll
    for (int i = 0; i < 4; i++) {
        int n = m0 + tm * 4 + i;
        if (n >= Nn) break;
#pragma unroll
        for (int j = 0; j < 8; j++) {
            int c = tn * 8 + j;
            if (c < 64) g_xl[n * 64 + c] = acc[i][j] + bl[c];
            else        g_xr[n * 64 + (c - 64)] = acc[i][j] + br[c - 64];
        }
    }
    // zero accumulators for layer 1
#pragma unroll
    for (int i = 0; i < 16; i++) {
        int idx = t + i * 256;
        int n = m0 + (idx >> 6);
        if (n < Nn) g_agg[n * 64 + (idx & 63)] = 0.0f;
    }
    if (t < 64 && m0 + t < Nn) g_den[m0 + t] = 0.0f;
}

// ---------------- segmented pool (batch sorted): elu fused -------------------------
__global__ __launch_bounds__(256) void pool_kernel(const int* __restrict__ batch,
                                                   const float* __restrict__ bias1) {
    int t = threadIdx.x;
    int h = t & 63;
    int c = t >> 6;
    int n0 = blockIdx.x * 64 + c * 16;
    float b1 = bias1[h];
    int cur = -1;
    float acc = 0.0f, cnt = 0.0f;
#pragma unroll 1
    for (int k = 0; k < 16; k++) {
        int n = n0 + k;
        if (n >= Nn) break;
        int b = batch[n];
        if (b != cur) {
            if (cur >= 0) {
                atomicAdd(&g_pool[cur * Hh + h], acc);
                if (h == 0) atomicAdd(&g_cnt[cur], cnt);
            }
            cur = b; acc = 0.0f; cnt = 0.0f;
        }
        float v = g_agg[n * 64 + h] / (g_den[n] + 1e-16f) + b1;
        v = v > 0.0f ? v : expm1f(v);
        acc += v; cnt += 1.0f;
    }
    if (cur >= 0) {
        atomicAdd(&g_pool[cur * Hh + h], acc);
        if (h == 0) atomicAdd(&g_cnt[cur], cnt);
    }
}

// ---------------- head (also re-zeroes g_cur for the NEXT call) --------------------
__global__ __launch_bounds__(FCH) void head_kernel(const float* __restrict__ fc1w,
                                                   const float* __restrict__ fc1b,
                                                   const float* __restrict__ fc2w,
                                                   const float* __restrict__ fc2b,
                                                   float* __restrict__ out) {
    __shared__ float sg[Hh];
    __shared__ float sfc[FCH];
    __shared__ float slog[NC];
    int g = blockIdx.x;
    int t = threadIdx.x;
    for (int i = g * FCH + t; i < Nn; i += Gg * FCH) g_cur[i] = 0;
    if (t < Hh) {
        float inv = 1.0f / fmaxf(g_cnt[g], 1.0f);
        sg[t] = g_pool[g * Hh + t] * inv;
    }
    __syncthreads();
    float a = fc1b[t];
#pragma unroll 8
    for (int k = 0; k < Hh; k++) a = fmaf(sg[k], fc1w[k * FCH + t], a);
    sfc[t] = fmaxf(a, 0.0f);
    __syncthreads();
    if (t < NC) {
        float z = fc2b[t];
#pragma unroll 8
        for (int k = 0; k < FCH; k++) z = fmaf(sfc[k], fc2w[k * NC + t], z);
        slog[t] = z;
    }
    __syncthreads();
    if (t == 0) {
        float l0 = slog[0], l1 = slog[1];
        float m = fmaxf(l0, l1);
        float lse = m + logf(expf(l0 - m) + expf(l1 - m));
        out[g * NC + 0] = l0 - lse;
        out[g * NC + 1] = l1 - lse;
    }
}

// -----------------------------------------------------------------------------------
extern "C" void kernel_launch(void* const* d_in, const int* in_sizes, int n_in,
                              void* d_out, int out_size) {
    const float* x      = (const float*)d_in[0];
    const int*   ei     = (const int*)d_in[1];
    const float* ea     = (const float*)d_in[2];
    const int*   batch  = (const int*)d_in[3];
    const float* Wl0    = (const float*)d_in[4];
    const float* bl0    = (const float*)d_in[5];
    const float* Wr0    = (const float*)d_in[6];
    const float* br0    = (const float*)d_in[7];
    const float* We0    = (const float*)d_in[8];
    const float* att0   = (const float*)d_in[9];
    const float* bias0  = (const float*)d_in[10];
    const float* Wl1    = (const float*)d_in[11];
    const float* bl1    = (const float*)d_in[12];
    const float* Wr1    = (const float*)d_in[13];
    const float* br1    = (const float*)d_in[14];
    const float* We1    = (const float*)d_in[15];
    const float* att1   = (const float*)d_in[16];
    const float* bias1  = (const float*)d_in[17];
    const float* fc1w   = (const float*)d_in[18];
    const float* fc1b   = (const float*)d_in[19];
    const float* fc2w   = (const float*)d_in[20];
    const float* fc2b   = (const float*)d_in[21];
    float* out = (float*)d_out;

    const int mgrid = (Nn + 63) / 64;                        // 782
    const int sgrid = (Ee / 8 + 255) / 256;                  // 782
    const int egrid = (Ee / CH + 15) / 16;                   // 3125 (exact)

    proj0_gemm_kernel<<<mgrid, 256>>>(x, Wl0, bl0, Wr0, br0, ei);   // + fused histogram
    scan_kernel<<<1, 1024>>>();
    scatter_kernel<<<sgrid, 256>>>(ei, ea);
    edge_q_kernel<<<egrid, 256>>>(We0, att0);
    proj1_gemm_kernel<<<mgrid, 256>>>(Wl1, bl1, Wr1, br1, bias0);
    edge_q_kernel<<<egrid, 256>>>(We1, att1);
    pool_kernel<<<mgrid, 256>>>(batch, bias1);
    head_kernel<<<Gg, FCH>>>(fc1w, fc1b, fc2w, fc2b, out);          // + re-zero g_cur
}